// round 5
// baseline (speedup 1.0000x reference)
#include <cuda_runtime.h>
#include <cuda_bf16.h>

// RandomPrompter: out[b,c,h,w] = x[b,c,h,w] + (patch inside per-sample 30x30 window)
// Shapes: x [256,3,224,224] f32, patch [1,3,30,30] f32, offsets [256,2] i32.
//
// Pure streaming (308 MB, zero reuse) at ~92% of HBM spec already. This round:
// Blackwell-only 256-bit vector ld/st (v8.f32 -> LDG.E.256/STG.256), one v8 per
// thread = same 32B/thread as the best MLP=2 float4 version but half the
// memory instructions and index math.

#define BATCH 256
#define CH    3
#define HH    224
#define WW    224
#define PSZ   30

#define W8        (WW / 8)                        // 28 v8-blocks per row
#define TOTAL_V8  (BATCH * CH * HH * W8)          // 4,816,896
#define TPB       256

__global__ __launch_bounds__(TPB) void random_prompter_kernel(
    const float* __restrict__ x,
    const float* __restrict__ patch,
    const int2* __restrict__ offsets,
    float* __restrict__ out)
{
    int v = blockIdx.x * TPB + threadIdx.x;   // grid is exact: no bounds check
    long long elem = (long long)v * 8;

    float r0, r1, r2, r3, r4, r5, r6, r7;
    asm volatile(
        "ld.global.cs.v8.f32 {%0,%1,%2,%3,%4,%5,%6,%7}, [%8];"
        : "=f"(r0), "=f"(r1), "=f"(r2), "=f"(r3),
          "=f"(r4), "=f"(r5), "=f"(r6), "=f"(r7)
        : "l"(x + elem));

    // Decompose: v = ((b*3 + c)*224 + h)*28 + w8
    int w8 = v % W8;
    int t  = v / W8;
    int h  = t % HH;
    int t2 = t / HH;
    int c  = t2 % CH;
    int b  = t2 / CH;

    int2 off = __ldg(&offsets[b]);   // (row, col), each in [0, 194)
    int dh = h - off.x;
    if ((unsigned)dh < (unsigned)PSZ) {
        const float* prow = patch + (c * PSZ + dh) * PSZ;
        int dw = w8 * 8 - off.y;     // patch-relative column of lane 0
        if ((unsigned)(dw + 0) < (unsigned)PSZ) r0 += __ldg(&prow[dw + 0]);
        if ((unsigned)(dw + 1) < (unsigned)PSZ) r1 += __ldg(&prow[dw + 1]);
        if ((unsigned)(dw + 2) < (unsigned)PSZ) r2 += __ldg(&prow[dw + 2]);
        if ((unsigned)(dw + 3) < (unsigned)PSZ) r3 += __ldg(&prow[dw + 3]);
        if ((unsigned)(dw + 4) < (unsigned)PSZ) r4 += __ldg(&prow[dw + 4]);
        if ((unsigned)(dw + 5) < (unsigned)PSZ) r5 += __ldg(&prow[dw + 5]);
        if ((unsigned)(dw + 6) < (unsigned)PSZ) r6 += __ldg(&prow[dw + 6]);
        if ((unsigned)(dw + 7) < (unsigned)PSZ) r7 += __ldg(&prow[dw + 7]);
    }

    asm volatile(
        "st.global.cs.v8.f32 [%0], {%1,%2,%3,%4,%5,%6,%7,%8};"
        :: "l"(out + elem),
           "f"(r0), "f"(r1), "f"(r2), "f"(r3),
           "f"(r4), "f"(r5), "f"(r6), "f"(r7)
        : "memory");
}

extern "C" void kernel_launch(void* const* d_in, const int* in_sizes, int n_in,
                              void* d_out, int out_size)
{
    const float* x     = (const float*)d_in[0];
    const float* patch = (const float*)d_in[1];
    const int2*  offs  = (const int2*)d_in[2];
    float*       out   = (float*)d_out;

    const int blocks = TOTAL_V8 / TPB;  // 18816, exact
    random_prompter_kernel<<<blocks, TPB>>>(x, patch, offs, out);
}